// round 15
// baseline (speedup 1.0000x reference)
#include <cuda_runtime.h>
#include <cuda_fp16.h>
#include <cstdint>

// ---------------------------------------------------------------------------
// GNN: L x { agg = scatter_add(h[src]*ew, dst); h = PReLU(LN(agg@Wrel + h@Wroot + b)) }
// then logits = LN(relu(h@W1+b1)) @ W2 + b2
// R15: R14 + half-warp-per-edge gather (uint4 row loads, 2 edges per warp
//      instruction -> half the LDG issue count).
// ---------------------------------------------------------------------------

#define MAXN 100000
#define MAXE 1600000
#define DD   128

__device__ __half g_h16a [MAXN * DD];
__device__ __half g_h16b [MAXN * DD];
__device__ __half g_agg16[MAXN * DD];
__device__ int    g_cnt [MAXN];       // zero at entry of every call (see place)
__device__ int    g_off [MAXN + 1];
__device__ int    g_bsum[128];
__device__ uint2  g_epack[MAXE];      // {src, weight-bits}

__device__ __forceinline__ uint32_t h2pack(float lo, float hi) {
    __half2 h = __floats2half2_rn(lo, hi);
    return *(uint32_t*)&h;
}
__device__ __forceinline__ void mma16(float c[4], uint32_t a0, uint32_t a1,
                                      uint32_t a2, uint32_t a3,
                                      uint32_t b0, uint32_t b1) {
    asm volatile(
        "mma.sync.aligned.m16n8k16.row.col.f32.f16.f16.f32 "
        "{%0,%1,%2,%3},{%4,%5,%6,%7},{%8,%9},{%0,%1,%2,%3};"
        : "+f"(c[0]), "+f"(c[1]), "+f"(c[2]), "+f"(c[3])
        : "r"(a0), "r"(a1), "r"(a2), "r"(a3), "r"(b0), "r"(b1));
}

// ======================= CSR build (no memsets) ============================
__global__ void hist_kernel(const int* __restrict__ ei, int* __restrict__ cnt, int E) {
    int e = blockIdx.x * blockDim.x + threadIdx.x;
    if (e < E) atomicAdd(cnt + __ldg(ei + E + e), 1);
}
__global__ void scan1_kernel(const int* __restrict__ cnt, int* __restrict__ off,
                             int* __restrict__ bsum, int N) {
    __shared__ int s[1024];
    int tid = threadIdx.x;
    int i = blockIdx.x * 1024 + tid;
    int v = (i < N) ? cnt[i] : 0;
    s[tid] = v; __syncthreads();
    #pragma unroll
    for (int d = 1; d < 1024; d <<= 1) {
        int t = (tid >= d) ? s[tid - d] : 0;
        __syncthreads();
        s[tid] += t;
        __syncthreads();
    }
    if (i < N) off[i] = s[tid] - v;
    if (tid == 1023) bsum[blockIdx.x] = s[1023];
}
__global__ void scan2_kernel(int* __restrict__ bsum, int* __restrict__ off,
                             int NB, int N) {
    __shared__ int s[128];
    int tid = threadIdx.x;
    int v = (tid < NB) ? bsum[tid] : 0;
    s[tid] = v; __syncthreads();
    #pragma unroll
    for (int d = 1; d < 128; d <<= 1) {
        int t = (tid >= d) ? s[tid - d] : 0;
        __syncthreads();
        s[tid] += t;
        __syncthreads();
    }
    if (tid < NB) bsum[tid] = s[tid] - v;
    if (tid == 127) off[N] = s[127];
}
__global__ void place_kernel(const int* __restrict__ ei, const float* __restrict__ ew,
                             const int* __restrict__ off, const int* __restrict__ bsum,
                             int* __restrict__ cursor, uint2* __restrict__ epack, int E) {
    int e = blockIdx.x * blockDim.x + threadIdx.x;
    if (e >= E) return;
    int src = __ldg(ei + e);
    int dst = __ldg(ei + E + e);
    int pos = off[dst] + bsum[dst >> 10] + (atomicSub(cursor + dst, 1) - 1);
    epack[pos] = make_uint2((uint32_t)src, __float_as_uint(__ldg(ew + e)));
}

// ======================= fp32 -> fp16 convert ==============================
__global__ void to_half_kernel(const float4* __restrict__ x,
                               uint2* __restrict__ y, int n4) {
    int i = blockIdx.x * blockDim.x + threadIdx.x;
    if (i >= n4) return;
    float4 v = x[i];
    __half2 a = __floats2half2_rn(v.x, v.y);
    __half2 b = __floats2half2_rn(v.z, v.w);
    y[i] = make_uint2(*(uint32_t*)&a, *(uint32_t*)&b);
}

// ===== Aggregation: warp per node, HALF-WARP per edge (uint4 row loads) ====
// Lane l16 = lane&15 covers columns l16*8 .. l16*8+7 (16 B). Half-warp 0
// handles edges beg, beg+2, ...; half-warp 1 handles beg+1, beg+3, ....
// Combine with shfl_xor(16); lower half writes the fp16 row.
__global__ __launch_bounds__(256)
void gather_kernel(const __half* __restrict__ h16,
                   const int*    __restrict__ off,
                   const int*    __restrict__ bsum,
                   const uint2*  __restrict__ epack,
                   __half*       __restrict__ agg16, int N) {
    int warp = threadIdx.x >> 5, lane = threadIdx.x & 31;
    int node = blockIdx.x * 8 + warp;
    if (node >= N) return;
    int hs  = lane >> 4;          // half-warp select
    int l16 = lane & 15;
    int beg = __ldg(off + node) + __ldg(bsum + (node >> 10));
    int end = (node + 1 == N) ? __ldg(off + N)
                              : __ldg(off + node + 1) + __ldg(bsum + ((node + 1) >> 10));

    float acc[8] = {0.f, 0.f, 0.f, 0.f, 0.f, 0.f, 0.f, 0.f};
    int e = beg + hs;
    // unroll-2: edges e and e+2 for this half-warp (batched independent loads)
    for (; e + 2 < end; e += 4) {
        uint2 E0 = __ldg(epack + e);
        uint2 E1 = __ldg(epack + e + 2);
        uint4 r0 = *reinterpret_cast<const uint4*>(h16 + (size_t)E0.x * DD + l16 * 8);
        uint4 r1 = *reinterpret_cast<const uint4*>(h16 + (size_t)E1.x * DD + l16 * 8);
        float w0 = __uint_as_float(E0.y), w1 = __uint_as_float(E1.y);
        const uint32_t* p0 = &r0.x;
        const uint32_t* p1 = &r1.x;
        #pragma unroll
        for (int j = 0; j < 4; j++) {
            float2 v0 = __half22float2(*(__half2*)&p0[j]);
            float2 v1 = __half22float2(*(__half2*)&p1[j]);
            acc[2*j]   = fmaf(w0, v0.x, fmaf(w1, v1.x, acc[2*j]));
            acc[2*j+1] = fmaf(w0, v0.y, fmaf(w1, v1.y, acc[2*j+1]));
        }
    }
    if (e < end) {
        uint2 E0 = __ldg(epack + e);
        uint4 r0 = *reinterpret_cast<const uint4*>(h16 + (size_t)E0.x * DD + l16 * 8);
        float w0 = __uint_as_float(E0.y);
        const uint32_t* p0 = &r0.x;
        #pragma unroll
        for (int j = 0; j < 4; j++) {
            float2 v0 = __half22float2(*(__half2*)&p0[j]);
            acc[2*j]   = fmaf(w0, v0.x, acc[2*j]);
            acc[2*j+1] = fmaf(w0, v0.y, acc[2*j+1]);
        }
    }
    // combine the two half-warps (columns identical, edges disjoint)
    #pragma unroll
    for (int j = 0; j < 8; j++)
        acc[j] += __shfl_xor_sync(0xffffffffu, acc[j], 16);
    if (hs == 0) {
        uint4 o;
        o.x = h2pack(acc[0], acc[1]);
        o.y = h2pack(acc[2], acc[3]);
        o.z = h2pack(acc[4], acc[5]);
        o.w = h2pack(acc[6], acc[7]);
        *reinterpret_cast<uint4*>(agg16 + (size_t)node * DD + l16 * 8) = o;
    }
}

// ============== Layer GEMM: warp mma.sync f16, A from fp16 arrays ==========
__global__ __launch_bounds__(256, 1)
void layer_mma_kernel(const __half* __restrict__ hin16,
                      const __half* __restrict__ agg16,
                      const float* __restrict__ Wrel,
                      const float* __restrict__ Wroot,
                      const float* __restrict__ bias,
                      const float* __restrict__ lng,
                      const float* __restrict__ lnb,
                      const float* __restrict__ alpha,
                      __half*      __restrict__ hout16,
                      int N) {
    extern __shared__ uint2 smem2[];
    uint2* sBr = smem2;            // 32 KB Wrel fragments
    uint2* sBo = smem2 + 4096;     // 32 KB Wroot fragments
    __shared__ float sBias[128], sG[128], sB2[128];

    int tid = threadIdx.x, wid = tid >> 5, lane = tid & 31;
    int g = lane >> 2, t = lane & 3;

    for (int idx = tid; idx < 4096; idx += 256) {
        int nt = idx >> 8, rem = idx & 255, kkp = rem >> 5, ln = rem & 31;
        int gg = ln >> 2, tt = ln & 3;
        int n = nt * 8 + gg, k0 = kkp * 16 + 2 * tt;
        sBr[idx] = make_uint2(
            h2pack(Wrel[(size_t)(k0)     * 128 + n], Wrel[(size_t)(k0 + 1) * 128 + n]),
            h2pack(Wrel[(size_t)(k0 + 8) * 128 + n], Wrel[(size_t)(k0 + 9) * 128 + n]));
        sBo[idx] = make_uint2(
            h2pack(Wroot[(size_t)(k0)     * 128 + n], Wroot[(size_t)(k0 + 1) * 128 + n]),
            h2pack(Wroot[(size_t)(k0 + 8) * 128 + n], Wroot[(size_t)(k0 + 9) * 128 + n]));
    }
    if (tid < 128) {
        sBias[tid] = __ldg(bias + tid);
        sG[tid]    = __ldg(lng + tid);
        sB2[tid]   = __ldg(lnb + tid);
    }
    __syncthreads();

    float al = __ldg(alpha);
    int numUnits = (N + 31) >> 5;
    int ustride  = gridDim.x * 8;

    for (int unit = blockIdx.x * 8 + wid; unit < numUnits; unit += ustride) {
        int R0 = unit * 32;
        float c[2][16][4];
        #pragma unroll
        for (int mt = 0; mt < 2; mt++)
            #pragma unroll
            for (int nt = 0; nt < 16; nt++)
                #pragma unroll
                for (int j = 0; j < 4; j++) c[mt][nt][j] = 0.f;

        #pragma unroll
        for (int half = 0; half < 2; half++) {
            const __half* src = half ? hin16 : agg16;
            const uint2*  sBf = half ? sBo : sBr;

            const __half* rp[2][2];
            bool rv[2][2];
            #pragma unroll
            for (int mt = 0; mt < 2; mt++)
                #pragma unroll
                for (int rh = 0; rh < 2; rh++) {
                    int r = R0 + mt * 16 + g + 8 * rh;
                    rv[mt][rh] = r < N;
                    rp[mt][rh] = src + (size_t)r * 128 + 2 * t;
                }

            uint32_t a[2][2][4];
            #pragma unroll
            for (int mt = 0; mt < 2; mt++) {
                a[0][mt][0] = rv[mt][0] ? *(const uint32_t*)(rp[mt][0])     : 0u;
                a[0][mt][1] = rv[mt][1] ? *(const uint32_t*)(rp[mt][1])     : 0u;
                a[0][mt][2] = rv[mt][0] ? *(const uint32_t*)(rp[mt][0] + 8) : 0u;
                a[0][mt][3] = rv[mt][1] ? *(const uint32_t*)(rp[mt][1] + 8) : 0u;
            }

            #pragma unroll
            for (int kkp = 0; kkp < 8; kkp++) {
                int cur = kkp & 1;
                if (kkp < 7) {
                    int o = (kkp + 1) * 16;
                    #pragma unroll
                    for (int mt = 0; mt < 2; mt++) {
                        a[cur^1][mt][0] = rv[mt][0] ? *(const uint32_t*)(rp[mt][0] + o)     : 0u;
                        a[cur^1][mt][1] = rv[mt][1] ? *(const uint32_t*)(rp[mt][1] + o)     : 0u;
                        a[cur^1][mt][2] = rv[mt][0] ? *(const uint32_t*)(rp[mt][0] + o + 8) : 0u;
                        a[cur^1][mt][3] = rv[mt][1] ? *(const uint32_t*)(rp[mt][1] + o + 8) : 0u;
                    }
                }
                #pragma unroll
                for (int nt = 0; nt < 16; nt++) {
                    uint2 bv = sBf[(nt << 8) + (kkp << 5) + lane];
                    mma16(c[0][nt], a[cur][0][0], a[cur][0][1], a[cur][0][2], a[cur][0][3], bv.x, bv.y);
                    mma16(c[1][nt], a[cur][1][0], a[cur][1][1], a[cur][1][2], a[cur][1][3], bv.x, bv.y);
                }
            }
        }

        // ---- epilogue: bias + LN + PReLU + fp16 store ----
        #pragma unroll
        for (int mt = 0; mt < 2; mt++) {
            #pragma unroll
            for (int rh = 0; rh < 2; rh++) {
                int r = R0 + mt * 16 + g + 8 * rh;
                float s = 0.f;
                #pragma unroll
                for (int nt = 0; nt < 16; nt++) {
                    int col = nt * 8 + 2 * t;
                    c[mt][nt][2*rh]   += sBias[col];
                    c[mt][nt][2*rh+1] += sBias[col + 1];
                    s += c[mt][nt][2*rh] + c[mt][nt][2*rh+1];
                }
                s += __shfl_xor_sync(0xffffffffu, s, 1);
                s += __shfl_xor_sync(0xffffffffu, s, 2);
                float mu = s * 0.0078125f;
                float q = 0.f;
                #pragma unroll
                for (int nt = 0; nt < 16; nt++) {
                    c[mt][nt][2*rh]   -= mu;
                    c[mt][nt][2*rh+1] -= mu;
                    q = fmaf(c[mt][nt][2*rh],   c[mt][nt][2*rh],
                        fmaf(c[mt][nt][2*rh+1], c[mt][nt][2*rh+1], q));
                }
                q += __shfl_xor_sync(0xffffffffu, q, 1);
                q += __shfl_xor_sync(0xffffffffu, q, 2);
                float rstd = rsqrtf(q * 0.0078125f + 1e-5f);
                if (r < N) {
                    #pragma unroll
                    for (int nt = 0; nt < 16; nt++) {
                        int col = nt * 8 + 2 * t;
                        float y0 = c[mt][nt][2*rh]   * rstd * sG[col]     + sB2[col];
                        float y1 = c[mt][nt][2*rh+1] * rstd * sG[col + 1] + sB2[col + 1];
                        y0 = y0 >= 0.f ? y0 : al * y0;
                        y1 = y1 >= 0.f ? y1 : al * y1;
                        *reinterpret_cast<__half2*>(hout16 + (size_t)r * 128 + col) =
                            __floats2half2_rn(y0, y1);
                    }
                }
            }
        }
    }
}

// ============== Classifier: warp mma.sync f16, A from fp16 =================
__global__ __launch_bounds__(256, 1)
void cls_mma_kernel(const __half* __restrict__ hin16,
                    const float* __restrict__ W1,
                    const float* __restrict__ b1,
                    const float* __restrict__ lng,
                    const float* __restrict__ lnb,
                    const float* __restrict__ W2,
                    const float* __restrict__ b2,
                    float*       __restrict__ out,
                    int N) {
    extern __shared__ uint2 smem2[];
    uint2* sBf = smem2;            // 32 KB W1 fragments
    __shared__ float sBias[128], sG[128], sB2[128], sW2[256];

    int tid = threadIdx.x, wid = tid >> 5, lane = tid & 31;
    int g = lane >> 2, t = lane & 3;

    for (int idx = tid; idx < 4096; idx += 256) {
        int nt = idx >> 8, rem = idx & 255, kkp = rem >> 5, ln = rem & 31;
        int gg = ln >> 2, tt = ln & 3;
        int n = nt * 8 + gg, k0 = kkp * 16 + 2 * tt;
        sBf[idx] = make_uint2(
            h2pack(W1[(size_t)(k0)     * 128 + n], W1[(size_t)(k0 + 1) * 128 + n]),
            h2pack(W1[(size_t)(k0 + 8) * 128 + n], W1[(size_t)(k0 + 9) * 128 + n]));
    }
    if (tid < 128) {
        sBias[tid] = __ldg(b1 + tid);
        sG[tid]    = __ldg(lng + tid);
        sB2[tid]   = __ldg(lnb + tid);
        sW2[tid * 2]     = __ldg(W2 + tid * 2);
        sW2[tid * 2 + 1] = __ldg(W2 + tid * 2 + 1);
    }
    __syncthreads();

    float b20 = __ldg(b2 + 0), b21 = __ldg(b2 + 1);
    int numUnits = (N + 31) >> 5;
    int ustride  = gridDim.x * 8;

    for (int unit = blockIdx.x * 8 + wid; unit < numUnits; unit += ustride) {
        int R0 = unit * 32;
        float c[2][16][4];
        #pragma unroll
        for (int mt = 0; mt < 2; mt++)
            #pragma unroll
            for (int nt = 0; nt < 16; nt++)
                #pragma unroll
                for (int j = 0; j < 4; j++) c[mt][nt][j] = 0.f;

        const __half* rp[2][2];
        bool rv[2][2];
        #pragma unroll
        for (int mt = 0; mt < 2; mt++)
            #pragma unroll
            for (int rh = 0; rh < 2; rh++) {
                int r = R0 + mt * 16 + g + 8 * rh;
                rv[mt][rh] = r < N;
                rp[mt][rh] = hin16 + (size_t)r * 128 + 2 * t;
            }

        uint32_t a[2][2][4];
        #pragma unroll
        for (int mt = 0; mt < 2; mt++) {
            a[0][mt][0] = rv[mt][0] ? *(const uint32_t*)(rp[mt][0])     : 0u;
            a[0][mt][1] = rv[mt][1] ? *(const uint32_t*)(rp[mt][1])     : 0u;
            a[0][mt][2] = rv[mt][0] ? *(const uint32_t*)(rp[mt][0] + 8) : 0u;
            a[0][mt][3] = rv[mt][1] ? *(const uint32_t*)(rp[mt][1] + 8) : 0u;
        }

        #pragma unroll
        for (int kkp = 0; kkp < 8; kkp++) {
            int cur = kkp & 1;
            if (kkp < 7) {
                int o = (kkp + 1) * 16;
                #pragma unroll
                for (int mt = 0; mt < 2; mt++) {
                    a[cur^1][mt][0] = rv[mt][0] ? *(const uint32_t*)(rp[mt][0] + o)     : 0u;
                    a[cur^1][mt][1] = rv[mt][1] ? *(const uint32_t*)(rp[mt][1] + o)     : 0u;
                    a[cur^1][mt][2] = rv[mt][0] ? *(const uint32_t*)(rp[mt][0] + o + 8) : 0u;
                    a[cur^1][mt][3] = rv[mt][1] ? *(const uint32_t*)(rp[mt][1] + o + 8) : 0u;
                }
            }
            #pragma unroll
            for (int nt = 0; nt < 16; nt++) {
                uint2 bv = sBf[(nt << 8) + (kkp << 5) + lane];
                mma16(c[0][nt], a[cur][0][0], a[cur][0][1], a[cur][0][2], a[cur][0][3], bv.x, bv.y);
                mma16(c[1][nt], a[cur][1][0], a[cur][1][1], a[cur][1][2], a[cur][1][3], bv.x, bv.y);
            }
        }

        // ---- epilogue: bias + ReLU + LN + W2 projection ----
        #pragma unroll
        for (int mt = 0; mt < 2; mt++) {
            #pragma unroll
            for (int rh = 0; rh < 2; rh++) {
                int r = R0 + mt * 16 + g + 8 * rh;
                float s = 0.f;
                #pragma unroll
                for (int nt = 0; nt < 16; nt++) {
                    int col = nt * 8 + 2 * t;
                    float v0 = fmaxf(c[mt][nt][2*rh]   + sBias[col],     0.f);
                    float v1 = fmaxf(c[mt][nt][2*rh+1] + sBias[col + 1], 0.f);
                    c[mt][nt][2*rh]   = v0;
                    c[mt][nt][2*rh+1] = v1;
                    s += v0 + v1;
                }
                s += __shfl_xor_sync(0xffffffffu, s, 1);
                s += __shfl_xor_sync(0xffffffffu, s, 2);
                float mu = s * 0.0078125f;
                float q = 0.f;
                #pragma unroll
                for (int nt = 0; nt < 16; nt++) {
                    c[mt][nt][2*rh]   -= mu;
                    c[mt][nt][2*rh+1] -= mu;
                    q = fmaf(c[mt][nt][2*rh],   c[mt][nt][2*rh],
                        fmaf(c[mt][nt][2*rh+1], c[mt][nt][2*rh+1], q));
                }
                q += __shfl_xor_sync(0xffffffffu, q, 1);
                q += __shfl_xor_sync(0xffffffffu, q, 2);
                float rstd = rsqrtf(q * 0.0078125f + 1e-5f);
                float p0 = 0.f, p1 = 0.f;
                #pragma unroll
                for (int nt = 0; nt < 16; nt++) {
                    int col = nt * 8 + 2 * t;
                    float z0 = c[mt][nt][2*rh]   * rstd * sG[col]     + sB2[col];
                    float z1 = c[mt][nt][2*rh+1] * rstd * sG[col + 1] + sB2[col + 1];
                    p0 = fmaf(z0, sW2[col * 2],     fmaf(z1, sW2[(col + 1) * 2],     p0));
                    p1 = fmaf(z0, sW2[col * 2 + 1], fmaf(z1, sW2[(col + 1) * 2 + 1], p1));
                }
                p0 += __shfl_xor_sync(0xffffffffu, p0, 1);
                p0 += __shfl_xor_sync(0xffffffffu, p0, 2);
                p1 += __shfl_xor_sync(0xffffffffu, p1, 1);
                p1 += __shfl_xor_sync(0xffffffffu, p1, 2);
                if (t == 0 && r < N) {
                    out[(size_t)r * 2 + 0] = p0 + b20;
                    out[(size_t)r * 2 + 1] = p1 + b21;
                }
            }
        }
    }
}

// ---------------------------------------------------------------------------
extern "C" void kernel_launch(void* const* d_in, const int* in_sizes, int n_in,
                              void* d_out, int out_size) {
    const float* features = (const float*)d_in[0];
    const int*   ei       = (const int*)  d_in[1];
    const float* ew       = (const float*)d_in[2];
    const float* Wrel     = (const float*)d_in[3];
    const float* Wroot    = (const float*)d_in[4];
    const float* bias     = (const float*)d_in[5];
    const float* lng      = (const float*)d_in[6];
    const float* lnb      = (const float*)d_in[7];
    const float* alpha    = (const float*)d_in[8];
    const float* W1       = (const float*)d_in[9];
    const float* b1       = (const float*)d_in[10];
    const float* cg       = (const float*)d_in[11];
    const float* cb       = (const float*)d_in[12];
    const float* W2       = (const float*)d_in[13];
    const float* b2       = (const float*)d_in[14];

    int N = in_sizes[0] / DD;
    int E = in_sizes[1] / 2;
    int L = in_sizes[8];

    __half *h16a, *h16b, *agg16;
    int *cnt, *off, *bsum;
    uint2 *epack;
    cudaGetSymbolAddress((void**)&h16a,  g_h16a);
    cudaGetSymbolAddress((void**)&h16b,  g_h16b);
    cudaGetSymbolAddress((void**)&agg16, g_agg16);
    cudaGetSymbolAddress((void**)&cnt,   g_cnt);
    cudaGetSymbolAddress((void**)&off,   g_off);
    cudaGetSymbolAddress((void**)&bsum,  g_bsum);
    cudaGetSymbolAddress((void**)&epack, g_epack);

    int sm = 148;
    cudaDeviceGetAttribute(&sm, cudaDevAttrMultiProcessorCount, 0);

    size_t smemL = 65536;   // 2 x 32 KB fp16 B fragments
    size_t smemC = 32768;   // 32 KB
    cudaFuncSetAttribute(layer_mma_kernel, cudaFuncAttributeMaxDynamicSharedMemorySize, (int)smemL);
    cudaFuncSetAttribute(cls_mma_kernel,   cudaFuncAttributeMaxDynamicSharedMemorySize, (int)smemC);

    // ---- CSR build (no memsets; cnt self-restores) ----
    int NB = (N + 1023) / 1024;
    hist_kernel <<<(E + 255) / 256, 256>>>(ei, cnt, E);
    scan1_kernel<<<NB, 1024>>>(cnt, off, bsum, N);
    scan2_kernel<<<1, 128>>>(bsum, off, NB, N);
    place_kernel<<<(E + 255) / 256, 256>>>(ei, ew, off, bsum, cnt, epack, E);

    // fp16 features -> h16a
    int n4 = N * DD / 4;
    to_half_kernel<<<(n4 + 255) / 256, 256>>>((const float4*)features, (uint2*)h16a, n4);

    int gatherBlocks = (N + 7) / 8;

    __half* hin = h16a;
    __half* pong[2] = { h16b, h16a };
    for (int i = 0; i < L; i++) {
        __half* hout = pong[i & 1];
        gather_kernel<<<gatherBlocks, 256>>>(hin, off, bsum, epack, agg16, N);
        layer_mma_kernel<<<sm, 256, smemL>>>(hin, agg16,
                                             Wrel  + (size_t)i * DD * DD,
                                             Wroot + (size_t)i * DD * DD,
                                             bias + i * DD, lng + i * DD, lnb + i * DD,
                                             alpha + i, hout, N);
        hin = hout;
    }
    cls_mma_kernel<<<sm, 256, smemC>>>(hin, W1, b1, cg, cb, W2, b2,
                                       (float*)d_out, N);
}

// round 16
// speedup vs baseline: 1.1869x; 1.1869x over previous
#include <cuda_runtime.h>
#include <cuda_fp16.h>
#include <cstdint>

// ---------------------------------------------------------------------------
// GNN: L x { agg = scatter_add(h[src]*ew, dst); h = PReLU(LN(agg@Wrel + h@Wroot + b)) }
// then logits = LN(relu(h@W1+b1)) @ W2 + b2
// R16: R14 (proven 309us) + PDL (programmatic dependent launch) on the
//      gather/layer/cls chain to overlap launch+prologue with producer drain.
// ---------------------------------------------------------------------------

#define MAXN 100000
#define MAXE 1600000
#define DD   128

__device__ __half g_h16a [MAXN * DD];
__device__ __half g_h16b [MAXN * DD];
__device__ __half g_agg16[MAXN * DD];
__device__ int    g_cnt [MAXN];       // zero at entry of every call (see place)
__device__ int    g_off [MAXN + 1];
__device__ int    g_bsum[128];
__device__ uint2  g_epack[MAXE];      // {src, weight-bits}

__device__ __forceinline__ void gdc_wait() {
    asm volatile("griddepcontrol.wait;" ::: "memory");
}
__device__ __forceinline__ void gdc_launch() {
    asm volatile("griddepcontrol.launch_dependents;" ::: "memory");
}
__device__ __forceinline__ uint32_t h2pack(float lo, float hi) {
    __half2 h = __floats2half2_rn(lo, hi);
    return *(uint32_t*)&h;
}
__device__ __forceinline__ void mma16(float c[4], uint32_t a0, uint32_t a1,
                                      uint32_t a2, uint32_t a3,
                                      uint32_t b0, uint32_t b1) {
    asm volatile(
        "mma.sync.aligned.m16n8k16.row.col.f32.f16.f16.f32 "
        "{%0,%1,%2,%3},{%4,%5,%6,%7},{%8,%9},{%0,%1,%2,%3};"
        : "+f"(c[0]), "+f"(c[1]), "+f"(c[2]), "+f"(c[3])
        : "r"(a0), "r"(a1), "r"(a2), "r"(a3), "r"(b0), "r"(b1));
}

// ======================= CSR build (no memsets) ============================
__global__ void hist_kernel(const int* __restrict__ ei, int* __restrict__ cnt, int E) {
    int e = blockIdx.x * blockDim.x + threadIdx.x;
    if (e < E) atomicAdd(cnt + __ldg(ei + E + e), 1);
}
__global__ void scan1_kernel(const int* __restrict__ cnt, int* __restrict__ off,
                             int* __restrict__ bsum, int N) {
    __shared__ int s[1024];
    int tid = threadIdx.x;
    int i = blockIdx.x * 1024 + tid;
    int v = (i < N) ? cnt[i] : 0;
    s[tid] = v; __syncthreads();
    #pragma unroll
    for (int d = 1; d < 1024; d <<= 1) {
        int t = (tid >= d) ? s[tid - d] : 0;
        __syncthreads();
        s[tid] += t;
        __syncthreads();
    }
    if (i < N) off[i] = s[tid] - v;
    if (tid == 1023) bsum[blockIdx.x] = s[1023];
}
__global__ void scan2_kernel(int* __restrict__ bsum, int* __restrict__ off,
                             int NB, int N) {
    __shared__ int s[128];
    int tid = threadIdx.x;
    int v = (tid < NB) ? bsum[tid] : 0;
    s[tid] = v; __syncthreads();
    #pragma unroll
    for (int d = 1; d < 128; d <<= 1) {
        int t = (tid >= d) ? s[tid - d] : 0;
        __syncthreads();
        s[tid] += t;
        __syncthreads();
    }
    if (tid < NB) bsum[tid] = s[tid] - v;
    if (tid == 127) off[N] = s[127];
}
__global__ void place_kernel(const int* __restrict__ ei, const float* __restrict__ ew,
                             const int* __restrict__ off, const int* __restrict__ bsum,
                             int* __restrict__ cursor, uint2* __restrict__ epack, int E) {
    int e = blockIdx.x * blockDim.x + threadIdx.x;
    if (e >= E) return;
    int src = __ldg(ei + e);
    int dst = __ldg(ei + E + e);
    int pos = off[dst] + bsum[dst >> 10] + (atomicSub(cursor + dst, 1) - 1);
    epack[pos] = make_uint2((uint32_t)src, __float_as_uint(__ldg(ew + e)));
}

// ======================= fp32 -> fp16 convert ==============================
__global__ void to_half_kernel(const float4* __restrict__ x,
                               uint2* __restrict__ y, int n4) {
    int i = blockIdx.x * blockDim.x + threadIdx.x;
    if (i >= n4) return;
    float4 v = x[i];
    __half2 a = __floats2half2_rn(v.x, v.y);
    __half2 b = __floats2half2_rn(v.z, v.w);
    y[i] = make_uint2(*(uint32_t*)&a, *(uint32_t*)&b);
}

// ======================= Aggregation: warp per node (R14 proven) ===========
__global__ __launch_bounds__(256)
void gather_kernel(const __half* __restrict__ h16,
                   const int*    __restrict__ off,
                   const int*    __restrict__ bsum,
                   const uint2*  __restrict__ epack,
                   __half*       __restrict__ agg16, int N) {
    int warp = threadIdx.x >> 5, lane = threadIdx.x & 31;
    int node = blockIdx.x * 8 + warp;
    if (node >= N) { gdc_wait(); return; }
    int beg = __ldg(off + node) + __ldg(bsum + (node >> 10));
    int end = (node + 1 == N) ? __ldg(off + N)
                              : __ldg(off + node + 1) + __ldg(bsum + ((node + 1) >> 10));
    gdc_wait();   // h16 comes from the producer kernel (to_half / prev layer)
    float4 acc = {0.f, 0.f, 0.f, 0.f};
    int e = beg;
    for (; e + 3 < end; e += 4) {
        uint2 E0 = __ldg(epack + e);
        uint2 E1 = __ldg(epack + e + 1);
        uint2 E2 = __ldg(epack + e + 2);
        uint2 E3 = __ldg(epack + e + 3);
        uint2 r0 = *reinterpret_cast<const uint2*>(h16 + (size_t)E0.x * DD + lane * 4);
        uint2 r1 = *reinterpret_cast<const uint2*>(h16 + (size_t)E1.x * DD + lane * 4);
        uint2 r2 = *reinterpret_cast<const uint2*>(h16 + (size_t)E2.x * DD + lane * 4);
        uint2 r3 = *reinterpret_cast<const uint2*>(h16 + (size_t)E3.x * DD + lane * 4);
        float w0 = __uint_as_float(E0.y), w1 = __uint_as_float(E1.y);
        float w2 = __uint_as_float(E2.y), w3 = __uint_as_float(E3.y);
        float2 a0 = __half22float2(*(__half2*)&r0.x), b0 = __half22float2(*(__half2*)&r0.y);
        float2 a1 = __half22float2(*(__half2*)&r1.x), b1 = __half22float2(*(__half2*)&r1.y);
        float2 a2 = __half22float2(*(__half2*)&r2.x), b2 = __half22float2(*(__half2*)&r2.y);
        float2 a3 = __half22float2(*(__half2*)&r3.x), b3 = __half22float2(*(__half2*)&r3.y);
        acc.x = fmaf(w0, a0.x, fmaf(w1, a1.x, fmaf(w2, a2.x, fmaf(w3, a3.x, acc.x))));
        acc.y = fmaf(w0, a0.y, fmaf(w1, a1.y, fmaf(w2, a2.y, fmaf(w3, a3.y, acc.y))));
        acc.z = fmaf(w0, b0.x, fmaf(w1, b1.x, fmaf(w2, b2.x, fmaf(w3, b3.x, acc.z))));
        acc.w = fmaf(w0, b0.y, fmaf(w1, b1.y, fmaf(w2, b2.y, fmaf(w3, b3.y, acc.w))));
    }
    for (; e < end; e++) {
        uint2 E0 = __ldg(epack + e);
        float w0 = __uint_as_float(E0.y);
        uint2 r0 = *reinterpret_cast<const uint2*>(h16 + (size_t)E0.x * DD + lane * 4);
        float2 a0 = __half22float2(*(__half2*)&r0.x);
        float2 b0 = __half22float2(*(__half2*)&r0.y);
        acc.x = fmaf(w0, a0.x, acc.x);
        acc.y = fmaf(w0, a0.y, acc.y);
        acc.z = fmaf(w0, b0.x, acc.z);
        acc.w = fmaf(w0, b0.y, acc.w);
    }
    *reinterpret_cast<uint2*>(agg16 + (size_t)node * DD + lane * 4) =
        make_uint2(h2pack(acc.x, acc.y), h2pack(acc.z, acc.w));
    gdc_launch();
}

// ============== Layer GEMM: warp mma.sync f16, A from fp16 arrays ==========
__global__ __launch_bounds__(256, 1)
void layer_mma_kernel(const __half* __restrict__ hin16,
                      const __half* __restrict__ agg16,
                      const float* __restrict__ Wrel,
                      const float* __restrict__ Wroot,
                      const float* __restrict__ bias,
                      const float* __restrict__ lng,
                      const float* __restrict__ lnb,
                      const float* __restrict__ alpha,
                      __half*      __restrict__ hout16,
                      int N) {
    extern __shared__ uint2 smem2[];
    uint2* sBr = smem2;            // 32 KB Wrel fragments
    uint2* sBo = smem2 + 4096;     // 32 KB Wroot fragments
    __shared__ float sBias[128], sG[128], sB2[128];

    int tid = threadIdx.x, wid = tid >> 5, lane = tid & 31;
    int g = lane >> 2, t = lane & 3;

    // ---- prologue: stage weights (inputs only; safe before gdc_wait) ----
    for (int idx = tid; idx < 4096; idx += 256) {
        int nt = idx >> 8, rem = idx & 255, kkp = rem >> 5, ln = rem & 31;
        int gg = ln >> 2, tt = ln & 3;
        int n = nt * 8 + gg, k0 = kkp * 16 + 2 * tt;
        sBr[idx] = make_uint2(
            h2pack(Wrel[(size_t)(k0)     * 128 + n], Wrel[(size_t)(k0 + 1) * 128 + n]),
            h2pack(Wrel[(size_t)(k0 + 8) * 128 + n], Wrel[(size_t)(k0 + 9) * 128 + n]));
        sBo[idx] = make_uint2(
            h2pack(Wroot[(size_t)(k0)     * 128 + n], Wroot[(size_t)(k0 + 1) * 128 + n]),
            h2pack(Wroot[(size_t)(k0 + 8) * 128 + n], Wroot[(size_t)(k0 + 9) * 128 + n]));
    }
    if (tid < 128) {
        sBias[tid] = __ldg(bias + tid);
        sG[tid]    = __ldg(lng + tid);
        sB2[tid]   = __ldg(lnb + tid);
    }
    __syncthreads();
    gdc_wait();   // agg16 comes from the producer gather

    float al = __ldg(alpha);
    int numUnits = (N + 31) >> 5;
    int ustride  = gridDim.x * 8;

    for (int unit = blockIdx.x * 8 + wid; unit < numUnits; unit += ustride) {
        int R0 = unit * 32;
        float c[2][16][4];
        #pragma unroll
        for (int mt = 0; mt < 2; mt++)
            #pragma unroll
            for (int nt = 0; nt < 16; nt++)
                #pragma unroll
                for (int j = 0; j < 4; j++) c[mt][nt][j] = 0.f;

        #pragma unroll
        for (int half = 0; half < 2; half++) {
            const __half* src = half ? hin16 : agg16;
            const uint2*  sBf = half ? sBo : sBr;

            const __half* rp[2][2];
            bool rv[2][2];
            #pragma unroll
            for (int mt = 0; mt < 2; mt++)
                #pragma unroll
                for (int rh = 0; rh < 2; rh++) {
                    int r = R0 + mt * 16 + g + 8 * rh;
                    rv[mt][rh] = r < N;
                    rp[mt][rh] = src + (size_t)r * 128 + 2 * t;
                }

            uint32_t a[2][2][4];
            #pragma unroll
            for (int mt = 0; mt < 2; mt++) {
                a[0][mt][0] = rv[mt][0] ? *(const uint32_t*)(rp[mt][0])     : 0u;
                a[0][mt][1] = rv[mt][1] ? *(const uint32_t*)(rp[mt][1])     : 0u;
                a[0][mt][2] = rv[mt][0] ? *(const uint32_t*)(rp[mt][0] + 8) : 0u;
                a[0][mt][3] = rv[mt][1] ? *(const uint32_t*)(rp[mt][1] + 8) : 0u;
            }

            #pragma unroll
            for (int kkp = 0; kkp < 8; kkp++) {
                int cur = kkp & 1;
                if (kkp < 7) {
                    int o = (kkp + 1) * 16;
                    #pragma unroll
                    for (int mt = 0; mt < 2; mt++) {
                        a[cur^1][mt][0] = rv[mt][0] ? *(const uint32_t*)(rp[mt][0] + o)     : 0u;
                        a[cur^1][mt][1] = rv[mt][1] ? *(const uint32_t*)(rp[mt][1] + o)     : 0u;
                        a[cur^1][mt][2] = rv[mt][0] ? *(const uint32_t*)(rp[mt][0] + o + 8) : 0u;
                        a[cur^1][mt][3] = rv[mt][1] ? *(const uint32_t*)(rp[mt][1] + o + 8) : 0u;
                    }
                }
                #pragma unroll
                for (int nt = 0; nt < 16; nt++) {
                    uint2 bv = sBf[(nt << 8) + (kkp << 5) + lane];
                    mma16(c[0][nt], a[cur][0][0], a[cur][0][1], a[cur][0][2], a[cur][0][3], bv.x, bv.y);
                    mma16(c[1][nt], a[cur][1][0], a[cur][1][1], a[cur][1][2], a[cur][1][3], bv.x, bv.y);
                }
            }
        }

        // ---- epilogue: bias + LN + PReLU + fp16 store ----
        #pragma unroll
        for (int mt = 0; mt < 2; mt++) {
            #pragma unroll
            for (int rh = 0; rh < 2; rh++) {
                int r = R0 + mt * 16 + g + 8 * rh;
                float s = 0.f;
                #pragma unroll
                for (int nt = 0; nt < 16; nt++) {
                    int col = nt * 8 + 2 * t;
                    c[mt][nt][2*rh]   += sBias[col];
                    c[mt][nt][2*rh+1] += sBias[col + 1];
                    s += c[mt][nt][2*rh] + c[mt][nt][2*rh+1];
                }
                s += __shfl_xor_sync(0xffffffffu, s, 1);
                s += __shfl_xor_sync(0xffffffffu, s, 2);
                float mu = s * 0.0078125f;
                float q = 0.f;
                #pragma unroll
                for (int nt = 0; nt < 16; nt++) {
                    c[mt][nt][2*rh]   -= mu;
                    c[mt][nt][2*rh+1] -= mu;
                    q = fmaf(c[mt][nt][2*rh],   c[mt][nt][2*rh],
                        fmaf(c[mt][nt][2*rh+1], c[mt][nt][2*rh+1], q));
                }
                q += __shfl_xor_sync(0xffffffffu, q, 1);
                q += __shfl_xor_sync(0xffffffffu, q, 2);
                float rstd = rsqrtf(q * 0.0078125f + 1e-5f);
                if (r < N) {
                    #pragma unroll
                    for (int nt = 0; nt < 16; nt++) {
                        int col = nt * 8 + 2 * t;
                        float y0 = c[mt][nt][2*rh]   * rstd * sG[col]     + sB2[col];
                        float y1 = c[mt][nt][2*rh+1] * rstd * sG[col + 1] + sB2[col + 1];
                        y0 = y0 >= 0.f ? y0 : al * y0;
                        y1 = y1 >= 0.f ? y1 : al * y1;
                        *reinterpret_cast<__half2*>(hout16 + (size_t)r * 128 + col) =
                            __floats2half2_rn(y0, y1);
                    }
                }
            }
        }
    }
    gdc_launch();
}

// ============== Classifier: warp mma.sync f16, A from fp16 =================
__global__ __launch_bounds__(256, 1)
void cls_mma_kernel(const __half* __restrict__ hin16,
                    const float* __restrict__ W1,
                    const float* __restrict__ b1,
                    const float* __restrict__ lng,
                    const float* __restrict__ lnb,
                    const float* __restrict__ W2,
                    const float* __restrict__ b2,
                    float*       __restrict__ out,
                    int N) {
    extern __shared__ uint2 smem2[];
    uint2* sBf = smem2;            // 32 KB W1 fragments
    __shared__ float sBias[128], sG[128], sB2[128], sW2[256];

    int tid = threadIdx.x, wid = tid >> 5, lane = tid & 31;
    int g = lane >> 2, t = lane & 3;

    for (int idx = tid; idx < 4096; idx += 256) {
        int nt = idx >> 8, rem = idx & 255, kkp = rem >> 5, ln = rem & 31;
        int gg = ln >> 2, tt = ln & 3;
        int n = nt * 8 + gg, k0 = kkp * 16 + 2 * tt;
        sBf[idx] = make_uint2(
            h2pack(W1[(size_t)(k0)     * 128 + n], W1[(size_t)(k0 + 1) * 128 + n]),
            h2pack(W1[(size_t)(k0 + 8) * 128 + n], W1[(size_t)(k0 + 9) * 128 + n]));
    }
    if (tid < 128) {
        sBias[tid] = __ldg(b1 + tid);
        sG[tid]    = __ldg(lng + tid);
        sB2[tid]   = __ldg(lnb + tid);
        sW2[tid * 2]     = __ldg(W2 + tid * 2);
        sW2[tid * 2 + 1] = __ldg(W2 + tid * 2 + 1);
    }
    __syncthreads();
    gdc_wait();   // hin16 comes from the producer layer

    float b20 = __ldg(b2 + 0), b21 = __ldg(b2 + 1);
    int numUnits = (N + 31) >> 5;
    int ustride  = gridDim.x * 8;

    for (int unit = blockIdx.x * 8 + wid; unit < numUnits; unit += ustride) {
        int R0 = unit * 32;
        float c[2][16][4];
        #pragma unroll
        for (int mt = 0; mt < 2; mt++)
            #pragma unroll
            for (int nt = 0; nt < 16; nt++)
                #pragma unroll
                for (int j = 0; j < 4; j++) c[mt][nt][j] = 0.f;

        const __half* rp[2][2];
        bool rv[2][2];
        #pragma unroll
        for (int mt = 0; mt < 2; mt++)
            #pragma unroll
            for (int rh = 0; rh < 2; rh++) {
                int r = R0 + mt * 16 + g + 8 * rh;
                rv[mt][rh] = r < N;
                rp[mt][rh] = hin16 + (size_t)r * 128 + 2 * t;
            }

        uint32_t a[2][2][4];
        #pragma unroll
        for (int mt = 0; mt < 2; mt++) {
            a[0][mt][0] = rv[mt][0] ? *(const uint32_t*)(rp[mt][0])     : 0u;
            a[0][mt][1] = rv[mt][1] ? *(const uint32_t*)(rp[mt][1])     : 0u;
            a[0][mt][2] = rv[mt][0] ? *(const uint32_t*)(rp[mt][0] + 8) : 0u;
            a[0][mt][3] = rv[mt][1] ? *(const uint32_t*)(rp[mt][1] + 8) : 0u;
        }

        #pragma unroll
        for (int kkp = 0; kkp < 8; kkp++) {
            int cur = kkp & 1;
            if (kkp < 7) {
                int o = (kkp + 1) * 16;
                #pragma unroll
                for (int mt = 0; mt < 2; mt++) {
                    a[cur^1][mt][0] = rv[mt][0] ? *(const uint32_t*)(rp[mt][0] + o)     : 0u;
                    a[cur^1][mt][1] = rv[mt][1] ? *(const uint32_t*)(rp[mt][1] + o)     : 0u;
                    a[cur^1][mt][2] = rv[mt][0] ? *(const uint32_t*)(rp[mt][0] + o + 8) : 0u;
                    a[cur^1][mt][3] = rv[mt][1] ? *(const uint32_t*)(rp[mt][1] + o + 8) : 0u;
                }
            }
            #pragma unroll
            for (int nt = 0; nt < 16; nt++) {
                uint2 bv = sBf[(nt << 8) + (kkp << 5) + lane];
                mma16(c[0][nt], a[cur][0][0], a[cur][0][1], a[cur][0][2], a[cur][0][3], bv.x, bv.y);
                mma16(c[1][nt], a[cur][1][0], a[cur][1][1], a[cur][1][2], a[cur][1][3], bv.x, bv.y);
            }
        }

        // ---- epilogue: bias + ReLU + LN + W2 projection ----
        #pragma unroll
        for (int mt = 0; mt < 2; mt++) {
            #pragma unroll
            for (int rh = 0; rh < 2; rh++) {
                int r = R0 + mt * 16 + g + 8 * rh;
                float s = 0.f;
                #pragma unroll
                for (int nt = 0; nt < 16; nt++) {
                    int col = nt * 8 + 2 * t;
                    float v0 = fmaxf(c[mt][nt][2*rh]   + sBias[col],     0.f);
                    float v1 = fmaxf(c[mt][nt][2*rh+1] + sBias[col + 1], 0.f);
                    c[mt][nt][2*rh]   = v0;
                    c[mt][nt][2*rh+1] = v1;
                    s += v0 + v1;
                }
                s += __shfl_xor_sync(0xffffffffu, s, 1);
                s += __shfl_xor_sync(0xffffffffu, s, 2);
                float mu = s * 0.0078125f;
                float q = 0.f;
                #pragma unroll
                for (int nt = 0; nt < 16; nt++) {
                    c[mt][nt][2*rh]   -= mu;
                    c[mt][nt][2*rh+1] -= mu;
                    q = fmaf(c[mt][nt][2*rh],   c[mt][nt][2*rh],
                        fmaf(c[mt][nt][2*rh+1], c[mt][nt][2*rh+1], q));
                }
                q += __shfl_xor_sync(0xffffffffu, q, 1);
                q += __shfl_xor_sync(0xffffffffu, q, 2);
                float rstd = rsqrtf(q * 0.0078125f + 1e-5f);
                float p0 = 0.f, p1 = 0.f;
                #pragma unroll
                for (int nt = 0; nt < 16; nt++) {
                    int col = nt * 8 + 2 * t;
                    float z0 = c[mt][nt][2*rh]   * rstd * sG[col]     + sB2[col];
                    float z1 = c[mt][nt][2*rh+1] * rstd * sG[col + 1] + sB2[col + 1];
                    p0 = fmaf(z0, sW2[col * 2],     fmaf(z1, sW2[(col + 1) * 2],     p0));
                    p1 = fmaf(z0, sW2[col * 2 + 1], fmaf(z1, sW2[(col + 1) * 2 + 1], p1));
                }
                p0 += __shfl_xor_sync(0xffffffffu, p0, 1);
                p0 += __shfl_xor_sync(0xffffffffu, p0, 2);
                p1 += __shfl_xor_sync(0xffffffffu, p1, 1);
                p1 += __shfl_xor_sync(0xffffffffu, p1, 2);
                if (t == 0 && r < N) {
                    out[(size_t)r * 2 + 0] = p0 + b20;
                    out[(size_t)r * 2 + 1] = p1 + b21;
                }
            }
        }
    }
}

// ---------------------------------------------------------------------------
extern "C" void kernel_launch(void* const* d_in, const int* in_sizes, int n_in,
                              void* d_out, int out_size) {
    const float* features = (const float*)d_in[0];
    const int*   ei       = (const int*)  d_in[1];
    const float* ew       = (const float*)d_in[2];
    const float* Wrel     = (const float*)d_in[3];
    const float* Wroot    = (const float*)d_in[4];
    const float* bias     = (const float*)d_in[5];
    const float* lng      = (const float*)d_in[6];
    const float* lnb      = (const float*)d_in[7];
    const float* alpha    = (const float*)d_in[8];
    const float* W1       = (const float*)d_in[9];
    const float* b1       = (const float*)d_in[10];
    const float* cg       = (const float*)d_in[11];
    const float* cb       = (const float*)d_in[12];
    const float* W2       = (const float*)d_in[13];
    const float* b2       = (const float*)d_in[14];

    int N = in_sizes[0] / DD;
    int E = in_sizes[1] / 2;
    int L = in_sizes[8];

    __half *h16a, *h16b, *agg16;
    int *cnt, *off, *bsum;
    uint2 *epack;
    cudaGetSymbolAddress((void**)&h16a,  g_h16a);
    cudaGetSymbolAddress((void**)&h16b,  g_h16b);
    cudaGetSymbolAddress((void**)&agg16, g_agg16);
    cudaGetSymbolAddress((void**)&cnt,   g_cnt);
    cudaGetSymbolAddress((void**)&off,   g_off);
    cudaGetSymbolAddress((void**)&bsum,  g_bsum);
    cudaGetSymbolAddress((void**)&epack, g_epack);

    int sm = 148;
    cudaDeviceGetAttribute(&sm, cudaDevAttrMultiProcessorCount, 0);

    size_t smemL = 65536;   // 2 x 32 KB fp16 B fragments
    size_t smemC = 32768;   // 32 KB
    cudaFuncSetAttribute(layer_mma_kernel, cudaFuncAttributeMaxDynamicSharedMemorySize, (int)smemL);
    cudaFuncSetAttribute(cls_mma_kernel,   cudaFuncAttributeMaxDynamicSharedMemorySize, (int)smemC);

    // ---- CSR build (no memsets; cnt self-restores) ----
    int NB = (N + 1023) / 1024;
    hist_kernel <<<(E + 255) / 256, 256>>>(ei, cnt, E);
    scan1_kernel<<<NB, 1024>>>(cnt, off, bsum, N);
    scan2_kernel<<<1, 128>>>(bsum, off, NB, N);
    place_kernel<<<(E + 255) / 256, 256>>>(ei, ew, off, bsum, cnt, epack, E);

    // fp16 features -> h16a
    int n4 = N * DD / 4;
    to_half_kernel<<<(n4 + 255) / 256, 256>>>((const float4*)features, (uint2*)h16a, n4);

    int gatherBlocks = (N + 7) / 8;

    // PDL launch attribute (programmatic stream serialization)
    cudaLaunchAttribute pdlAttr[1];
    pdlAttr[0].id = cudaLaunchAttributeProgrammaticStreamSerialization;
    pdlAttr[0].val.programmaticStreamSerializationAllowed = 1;

    __half* hin = h16a;
    __half* pong[2] = { h16b, h16a };
    for (int i = 0; i < L; i++) {
        __half* hout = pong[i & 1];

        cudaLaunchConfig_t cfgG = {};
        cfgG.gridDim  = dim3(gatherBlocks, 1, 1);
        cfgG.blockDim = dim3(256, 1, 1);
        cfgG.attrs    = pdlAttr;
        cfgG.numAttrs = 1;
        cudaLaunchKernelEx(&cfgG, gather_kernel,
                           (const __half*)hin, (const int*)off, (const int*)bsum,
                           (const uint2*)epack, agg16, N);

        cudaLaunchConfig_t cfgL = {};
        cfgL.gridDim          = dim3(sm, 1, 1);
        cfgL.blockDim         = dim3(256, 1, 1);
        cfgL.dynamicSmemBytes = smemL;
        cfgL.attrs            = pdlAttr;
        cfgL.numAttrs         = 1;
        cudaLaunchKernelEx(&cfgL, layer_mma_kernel,
                           (const __half*)hin, (const __half*)agg16,
                           (const float*)(Wrel  + (size_t)i * DD * DD),
                           (const float*)(Wroot + (size_t)i * DD * DD),
                           (const float*)(bias + i * DD), (const float*)(lng + i * DD),
                           (const float*)(lnb + i * DD), (const float*)(alpha + i),
                           hout, N);
        hin = hout;
    }

    cudaLaunchConfig_t cfgC = {};
    cfgC.gridDim          = dim3(sm, 1, 1);
    cfgC.blockDim         = dim3(256, 1, 1);
    cfgC.dynamicSmemBytes = smemC;
    cfgC.attrs            = pdlAttr;
    cfgC.numAttrs         = 1;
    cudaLaunchKernelEx(&cfgC, cls_mma_kernel,
                       (const __half*)hin, W1, b1, cg, cb, W2, b2,
                       (float*)d_out, N);
}

// round 17
// speedup vs baseline: 1.1989x; 1.0101x over previous
#include <cuda_runtime.h>
#include <cuda_fp16.h>
#include <cstdint>

// ---------------------------------------------------------------------------
// GNN: L x { agg = scatter_add(h[src]*ew, dst); h = PReLU(LN(agg@Wrel + h@Wroot + b)) }
// then logits = LN(relu(h@W1+b1)) @ W2 + b2
// R17: R16 (proven 298us) + PDL extended to ALL launches (CSR build + to_half
//      prelude included): every kernel waits at entry / signals at exit.
// ---------------------------------------------------------------------------

#define MAXN 100000
#define MAXE 1600000
#define DD   128

__device__ __half g_h16a [MAXN * DD];
__device__ __half g_h16b [MAXN * DD];
__device__ __half g_agg16[MAXN * DD];
__device__ int    g_cnt [MAXN];       // zero at entry of every call (see place)
__device__ int    g_off [MAXN + 1];
__device__ int    g_bsum[128];
__device__ uint2  g_epack[MAXE];      // {src, weight-bits}

__device__ __forceinline__ void gdc_wait() {
    asm volatile("griddepcontrol.wait;" ::: "memory");
}
__device__ __forceinline__ void gdc_launch() {
    asm volatile("griddepcontrol.launch_dependents;" ::: "memory");
}
__device__ __forceinline__ uint32_t h2pack(float lo, float hi) {
    __half2 h = __floats2half2_rn(lo, hi);
    return *(uint32_t*)&h;
}
__device__ __forceinline__ void mma16(float c[4], uint32_t a0, uint32_t a1,
                                      uint32_t a2, uint32_t a3,
                                      uint32_t b0, uint32_t b1) {
    asm volatile(
        "mma.sync.aligned.m16n8k16.row.col.f32.f16.f16.f32 "
        "{%0,%1,%2,%3},{%4,%5,%6,%7},{%8,%9},{%0,%1,%2,%3};"
        : "+f"(c[0]), "+f"(c[1]), "+f"(c[2]), "+f"(c[3])
        : "r"(a0), "r"(a1), "r"(a2), "r"(a3), "r"(b0), "r"(b1));
}

// ======================= CSR build (no memsets) ============================
__global__ void hist_kernel(const int* __restrict__ ei, int* __restrict__ cnt, int E) {
    gdc_wait();
    int e = blockIdx.x * blockDim.x + threadIdx.x;
    if (e < E) atomicAdd(cnt + __ldg(ei + E + e), 1);
    gdc_launch();
}
__global__ void scan1_kernel(const int* __restrict__ cnt, int* __restrict__ off,
                             int* __restrict__ bsum, int N) {
    gdc_wait();
    __shared__ int s[1024];
    int tid = threadIdx.x;
    int i = blockIdx.x * 1024 + tid;
    int v = (i < N) ? cnt[i] : 0;
    s[tid] = v; __syncthreads();
    #pragma unroll
    for (int d = 1; d < 1024; d <<= 1) {
        int t = (tid >= d) ? s[tid - d] : 0;
        __syncthreads();
        s[tid] += t;
        __syncthreads();
    }
    if (i < N) off[i] = s[tid] - v;
    if (tid == 1023) bsum[blockIdx.x] = s[1023];
    gdc_launch();
}
__global__ void scan2_kernel(int* __restrict__ bsum, int* __restrict__ off,
                             int NB, int N) {
    gdc_wait();
    __shared__ int s[128];
    int tid = threadIdx.x;
    int v = (tid < NB) ? bsum[tid] : 0;
    s[tid] = v; __syncthreads();
    #pragma unroll
    for (int d = 1; d < 128; d <<= 1) {
        int t = (tid >= d) ? s[tid - d] : 0;
        __syncthreads();
        s[tid] += t;
        __syncthreads();
    }
    if (tid < NB) bsum[tid] = s[tid] - v;
    if (tid == 127) off[N] = s[127];
    gdc_launch();
}
__global__ void place_kernel(const int* __restrict__ ei, const float* __restrict__ ew,
                             const int* __restrict__ off, const int* __restrict__ bsum,
                             int* __restrict__ cursor, uint2* __restrict__ epack, int E) {
    gdc_wait();
    int e = blockIdx.x * blockDim.x + threadIdx.x;
    if (e < E) {
        int src = __ldg(ei + e);
        int dst = __ldg(ei + E + e);
        int pos = off[dst] + bsum[dst >> 10] + (atomicSub(cursor + dst, 1) - 1);
        epack[pos] = make_uint2((uint32_t)src, __float_as_uint(__ldg(ew + e)));
    }
    gdc_launch();
}

// ======================= fp32 -> fp16 convert ==============================
__global__ void to_half_kernel(const float4* __restrict__ x,
                               uint2* __restrict__ y, int n4) {
    gdc_wait();
    int i = blockIdx.x * blockDim.x + threadIdx.x;
    if (i < n4) {
        float4 v = x[i];
        __half2 a = __floats2half2_rn(v.x, v.y);
        __half2 b = __floats2half2_rn(v.z, v.w);
        y[i] = make_uint2(*(uint32_t*)&a, *(uint32_t*)&b);
    }
    gdc_launch();
}

// ======================= Aggregation: warp per node (R14 proven) ===========
__global__ __launch_bounds__(256)
void gather_kernel(const __half* __restrict__ h16,
                   const int*    __restrict__ off,
                   const int*    __restrict__ bsum,
                   const uint2*  __restrict__ epack,
                   __half*       __restrict__ agg16, int N) {
    int warp = threadIdx.x >> 5, lane = threadIdx.x & 31;
    int node = blockIdx.x * 8 + warp;
    if (node >= N) { gdc_wait(); gdc_launch(); return; }
    int beg = __ldg(off + node) + __ldg(bsum + (node >> 10));
    int end = (node + 1 == N) ? __ldg(off + N)
                              : __ldg(off + node + 1) + __ldg(bsum + ((node + 1) >> 10));
    gdc_wait();   // h16 comes from the immediate producer (to_half / prev layer)
    float4 acc = {0.f, 0.f, 0.f, 0.f};
    int e = beg;
    for (; e + 3 < end; e += 4) {
        uint2 E0 = __ldg(epack + e);
        uint2 E1 = __ldg(epack + e + 1);
        uint2 E2 = __ldg(epack + e + 2);
        uint2 E3 = __ldg(epack + e + 3);
        uint2 r0 = *reinterpret_cast<const uint2*>(h16 + (size_t)E0.x * DD + lane * 4);
        uint2 r1 = *reinterpret_cast<const uint2*>(h16 + (size_t)E1.x * DD + lane * 4);
        uint2 r2 = *reinterpret_cast<const uint2*>(h16 + (size_t)E2.x * DD + lane * 4);
        uint2 r3 = *reinterpret_cast<const uint2*>(h16 + (size_t)E3.x * DD + lane * 4);
        float w0 = __uint_as_float(E0.y), w1 = __uint_as_float(E1.y);
        float w2 = __uint_as_float(E2.y), w3 = __uint_as_float(E3.y);
        float2 a0 = __half22float2(*(__half2*)&r0.x), b0 = __half22float2(*(__half2*)&r0.y);
        float2 a1 = __half22float2(*(__half2*)&r1.x), b1 = __half22float2(*(__half2*)&r1.y);
        float2 a2 = __half22float2(*(__half2*)&r2.x), b2 = __half22float2(*(__half2*)&r2.y);
        float2 a3 = __half22float2(*(__half2*)&r3.x), b3 = __half22float2(*(__half2*)&r3.y);
        acc.x = fmaf(w0, a0.x, fmaf(w1, a1.x, fmaf(w2, a2.x, fmaf(w3, a3.x, acc.x))));
        acc.y = fmaf(w0, a0.y, fmaf(w1, a1.y, fmaf(w2, a2.y, fmaf(w3, a3.y, acc.y))));
        acc.z = fmaf(w0, b0.x, fmaf(w1, b1.x, fmaf(w2, b2.x, fmaf(w3, b3.x, acc.z))));
        acc.w = fmaf(w0, b0.y, fmaf(w1, b1.y, fmaf(w2, b2.y, fmaf(w3, b3.y, acc.w))));
    }
    for (; e < end; e++) {
        uint2 E0 = __ldg(epack + e);
        float w0 = __uint_as_float(E0.y);
        uint2 r0 = *reinterpret_cast<const uint2*>(h16 + (size_t)E0.x * DD + lane * 4);
        float2 a0 = __half22float2(*(__half2*)&r0.x);
        float2 b0 = __half22float2(*(__half2*)&r0.y);
        acc.x = fmaf(w0, a0.x, acc.x);
        acc.y = fmaf(w0, a0.y, acc.y);
        acc.z = fmaf(w0, b0.x, acc.z);
        acc.w = fmaf(w0, b0.y, acc.w);
    }
    *reinterpret_cast<uint2*>(agg16 + (size_t)node * DD + lane * 4) =
        make_uint2(h2pack(acc.x, acc.y), h2pack(acc.z, acc.w));
    gdc_launch();
}

// ============== Layer GEMM: warp mma.sync f16, A from fp16 arrays ==========
__global__ __launch_bounds__(256, 1)
void layer_mma_kernel(const __half* __restrict__ hin16,
                      const __half* __restrict__ agg16,
                      const float* __restrict__ Wrel,
                      const float* __restrict__ Wroot,
                      const float* __restrict__ bias,
                      const float* __restrict__ lng,
                      const float* __restrict__ lnb,
                      const float* __restrict__ alpha,
                      __half*      __restrict__ hout16,
                      int N) {
    extern __shared__ uint2 smem2[];
    uint2* sBr = smem2;            // 32 KB Wrel fragments
    uint2* sBo = smem2 + 4096;     // 32 KB Wroot fragments
    __shared__ float sBias[128], sG[128], sB2[128];

    int tid = threadIdx.x, wid = tid >> 5, lane = tid & 31;
    int g = lane >> 2, t = lane & 3;

    // ---- prologue: stage weights (inputs only; safe before gdc_wait) ----
    for (int idx = tid; idx < 4096; idx += 256) {
        int nt = idx >> 8, rem = idx & 255, kkp = rem >> 5, ln = rem & 31;
        int gg = ln >> 2, tt = ln & 3;
        int n = nt * 8 + gg, k0 = kkp * 16 + 2 * tt;
        sBr[idx] = make_uint2(
            h2pack(Wrel[(size_t)(k0)     * 128 + n], Wrel[(size_t)(k0 + 1) * 128 + n]),
            h2pack(Wrel[(size_t)(k0 + 8) * 128 + n], Wrel[(size_t)(k0 + 9) * 128 + n]));
        sBo[idx] = make_uint2(
            h2pack(Wroot[(size_t)(k0)     * 128 + n], Wroot[(size_t)(k0 + 1) * 128 + n]),
            h2pack(Wroot[(size_t)(k0 + 8) * 128 + n], Wroot[(size_t)(k0 + 9) * 128 + n]));
    }
    if (tid < 128) {
        sBias[tid] = __ldg(bias + tid);
        sG[tid]    = __ldg(lng + tid);
        sB2[tid]   = __ldg(lnb + tid);
    }
    __syncthreads();
    gdc_wait();   // agg16 comes from the producer gather

    float al = __ldg(alpha);
    int numUnits = (N + 31) >> 5;
    int ustride  = gridDim.x * 8;

    for (int unit = blockIdx.x * 8 + wid; unit < numUnits; unit += ustride) {
        int R0 = unit * 32;
        float c[2][16][4];
        #pragma unroll
        for (int mt = 0; mt < 2; mt++)
            #pragma unroll
            for (int nt = 0; nt < 16; nt++)
                #pragma unroll
                for (int j = 0; j < 4; j++) c[mt][nt][j] = 0.f;

        #pragma unroll
        for (int half = 0; half < 2; half++) {
            const __half* src = half ? hin16 : agg16;
            const uint2*  sBf = half ? sBo : sBr;

            const __half* rp[2][2];
            bool rv[2][2];
            #pragma unroll
            for (int mt = 0; mt < 2; mt++)
                #pragma unroll
                for (int rh = 0; rh < 2; rh++) {
                    int r = R0 + mt * 16 + g + 8 * rh;
                    rv[mt][rh] = r < N;
                    rp[mt][rh] = src + (size_t)r * 128 + 2 * t;
                }

            uint32_t a[2][2][4];
            #pragma unroll
            for (int mt = 0; mt < 2; mt++) {
                a[0][mt][0] = rv[mt][0] ? *(const uint32_t*)(rp[mt][0])     : 0u;
                a[0][mt][1] = rv[mt][1] ? *(const uint32_t*)(rp[mt][1])     : 0u;
                a[0][mt][2] = rv[mt][0] ? *(const uint32_t*)(rp[mt][0] + 8) : 0u;
                a[0][mt][3] = rv[mt][1] ? *(const uint32_t*)(rp[mt][1] + 8) : 0u;
            }

            #pragma unroll
            for (int kkp = 0; kkp < 8; kkp++) {
                int cur = kkp & 1;
                if (kkp < 7) {
                    int o = (kkp + 1) * 16;
                    #pragma unroll
                    for (int mt = 0; mt < 2; mt++) {
                        a[cur^1][mt][0] = rv[mt][0] ? *(const uint32_t*)(rp[mt][0] + o)     : 0u;
                        a[cur^1][mt][1] = rv[mt][1] ? *(const uint32_t*)(rp[mt][1] + o)     : 0u;
                        a[cur^1][mt][2] = rv[mt][0] ? *(const uint32_t*)(rp[mt][0] + o + 8) : 0u;
                        a[cur^1][mt][3] = rv[mt][1] ? *(const uint32_t*)(rp[mt][1] + o + 8) : 0u;
                    }
                }
                #pragma unroll
                for (int nt = 0; nt < 16; nt++) {
                    uint2 bv = sBf[(nt << 8) + (kkp << 5) + lane];
                    mma16(c[0][nt], a[cur][0][0], a[cur][0][1], a[cur][0][2], a[cur][0][3], bv.x, bv.y);
                    mma16(c[1][nt], a[cur][1][0], a[cur][1][1], a[cur][1][2], a[cur][1][3], bv.x, bv.y);
                }
            }
        }

        // ---- epilogue: bias + LN + PReLU + fp16 store ----
        #pragma unroll
        for (int mt = 0; mt < 2; mt++) {
            #pragma unroll
            for (int rh = 0; rh < 2; rh++) {
                int r = R0 + mt * 16 + g + 8 * rh;
                float s = 0.f;
                #pragma unroll
                for (int nt = 0; nt < 16; nt++) {
                    int col = nt * 8 + 2 * t;
                    c[mt][nt][2*rh]   += sBias[col];
                    c[mt][nt][2*rh+1] += sBias[col + 1];
                    s += c[mt][nt][2*rh] + c[mt][nt][2*rh+1];
                }
                s += __shfl_xor_sync(0xffffffffu, s, 1);
                s += __shfl_xor_sync(0xffffffffu, s, 2);
                float mu = s * 0.0078125f;
                float q = 0.f;
                #pragma unroll
                for (int nt = 0; nt < 16; nt++) {
                    c[mt][nt][2*rh]   -= mu;
                    c[mt][nt][2*rh+1] -= mu;
                    q = fmaf(c[mt][nt][2*rh],   c[mt][nt][2*rh],
                        fmaf(c[mt][nt][2*rh+1], c[mt][nt][2*rh+1], q));
                }
                q += __shfl_xor_sync(0xffffffffu, q, 1);
                q += __shfl_xor_sync(0xffffffffu, q, 2);
                float rstd = rsqrtf(q * 0.0078125f + 1e-5f);
                if (r < N) {
                    #pragma unroll
                    for (int nt = 0; nt < 16; nt++) {
                        int col = nt * 8 + 2 * t;
                        float y0 = c[mt][nt][2*rh]   * rstd * sG[col]     + sB2[col];
                        float y1 = c[mt][nt][2*rh+1] * rstd * sG[col + 1] + sB2[col + 1];
                        y0 = y0 >= 0.f ? y0 : al * y0;
                        y1 = y1 >= 0.f ? y1 : al * y1;
                        *reinterpret_cast<__half2*>(hout16 + (size_t)r * 128 + col) =
                            __floats2half2_rn(y0, y1);
                    }
                }
            }
        }
    }
    gdc_launch();
}

// ============== Classifier: warp mma.sync f16, A from fp16 =================
__global__ __launch_bounds__(256, 1)
void cls_mma_kernel(const __half* __restrict__ hin16,
                    const float* __restrict__ W1,
                    const float* __restrict__ b1,
                    const float* __restrict__ lng,
                    const float* __restrict__ lnb,
                    const float* __restrict__ W2,
                    const float* __restrict__ b2,
                    float*       __restrict__ out,
                    int N) {
    extern __shared__ uint2 smem2[];
    uint2* sBf = smem2;            // 32 KB W1 fragments
    __shared__ float sBias[128], sG[128], sB2[128], sW2[256];

    int tid = threadIdx.x, wid = tid >> 5, lane = tid & 31;
    int g = lane >> 2, t = lane & 3;

    for (int idx = tid; idx < 4096; idx += 256) {
        int nt = idx >> 8, rem = idx & 255, kkp = rem >> 5, ln = rem & 31;
        int gg = ln >> 2, tt = ln & 3;
        int n = nt * 8 + gg, k0 = kkp * 16 + 2 * tt;
        sBf[idx] = make_uint2(
            h2pack(W1[(size_t)(k0)     * 128 + n], W1[(size_t)(k0 + 1) * 128 + n]),
            h2pack(W1[(size_t)(k0 + 8) * 128 + n], W1[(size_t)(k0 + 9) * 128 + n]));
    }
    if (tid < 128) {
        sBias[tid] = __ldg(b1 + tid);
        sG[tid]    = __ldg(lng + tid);
        sB2[tid]   = __ldg(lnb + tid);
        sW2[tid * 2]     = __ldg(W2 + tid * 2);
        sW2[tid * 2 + 1] = __ldg(W2 + tid * 2 + 1);
    }
    __syncthreads();
    gdc_wait();   // hin16 comes from the producer layer

    float b20 = __ldg(b2 + 0), b21 = __ldg(b2 + 1);
    int numUnits = (N + 31) >> 5;
    int ustride  = gridDim.x * 8;

    for (int unit = blockIdx.x * 8 + wid; unit < numUnits; unit += ustride) {
        int R0 = unit * 32;
        float c[2][16][4];
        #pragma unroll
        for (int mt = 0; mt < 2; mt++)
            #pragma unroll
            for (int nt = 0; nt < 16; nt++)
                #pragma unroll
                for (int j = 0; j < 4; j++) c[mt][nt][j] = 0.f;

        const __half* rp[2][2];
        bool rv[2][2];
        #pragma unroll
        for (int mt = 0; mt < 2; mt++)
            #pragma unroll
            for (int rh = 0; rh < 2; rh++) {
                int r = R0 + mt * 16 + g + 8 * rh;
                rv[mt][rh] = r < N;
                rp[mt][rh] = hin16 + (size_t)r * 128 + 2 * t;
            }

        uint32_t a[2][2][4];
        #pragma unroll
        for (int mt = 0; mt < 2; mt++) {
            a[0][mt][0] = rv[mt][0] ? *(const uint32_t*)(rp[mt][0])     : 0u;
            a[0][mt][1] = rv[mt][1] ? *(const uint32_t*)(rp[mt][1])     : 0u;
            a[0][mt][2] = rv[mt][0] ? *(const uint32_t*)(rp[mt][0] + 8) : 0u;
            a[0][mt][3] = rv[mt][1] ? *(const uint32_t*)(rp[mt][1] + 8) : 0u;
        }

        #pragma unroll
        for (int kkp = 0; kkp < 8; kkp++) {
            int cur = kkp & 1;
            if (kkp < 7) {
                int o = (kkp + 1) * 16;
                #pragma unroll
                for (int mt = 0; mt < 2; mt++) {
                    a[cur^1][mt][0] = rv[mt][0] ? *(const uint32_t*)(rp[mt][0] + o)     : 0u;
                    a[cur^1][mt][1] = rv[mt][1] ? *(const uint32_t*)(rp[mt][1] + o)     : 0u;
                    a[cur^1][mt][2] = rv[mt][0] ? *(const uint32_t*)(rp[mt][0] + o + 8) : 0u;
                    a[cur^1][mt][3] = rv[mt][1] ? *(const uint32_t*)(rp[mt][1] + o + 8) : 0u;
                }
            }
            #pragma unroll
            for (int nt = 0; nt < 16; nt++) {
                uint2 bv = sBf[(nt << 8) + (kkp << 5) + lane];
                mma16(c[0][nt], a[cur][0][0], a[cur][0][1], a[cur][0][2], a[cur][0][3], bv.x, bv.y);
                mma16(c[1][nt], a[cur][1][0], a[cur][1][1], a[cur][1][2], a[cur][1][3], bv.x, bv.y);
            }
        }

        // ---- epilogue: bias + ReLU + LN + W2 projection ----
        #pragma unroll
        for (int mt = 0; mt < 2; mt++) {
            #pragma unroll
            for (int rh = 0; rh < 2; rh++) {
                int r = R0 + mt * 16 + g + 8 * rh;
                float s = 0.f;
                #pragma unroll
                for (int nt = 0; nt < 16; nt++) {
                    int col = nt * 8 + 2 * t;
                    float v0 = fmaxf(c[mt][nt][2*rh]   + sBias[col],     0.f);
                    float v1 = fmaxf(c[mt][nt][2*rh+1] + sBias[col + 1], 0.f);
                    c[mt][nt][2*rh]   = v0;
                    c[mt][nt][2*rh+1] = v1;
                    s += v0 + v1;
                }
                s += __shfl_xor_sync(0xffffffffu, s, 1);
                s += __shfl_xor_sync(0xffffffffu, s, 2);
                float mu = s * 0.0078125f;
                float q = 0.f;
                #pragma unroll
                for (int nt = 0; nt < 16; nt++) {
                    c[mt][nt][2*rh]   -= mu;
                    c[mt][nt][2*rh+1] -= mu;
                    q = fmaf(c[mt][nt][2*rh],   c[mt][nt][2*rh],
                        fmaf(c[mt][nt][2*rh+1], c[mt][nt][2*rh+1], q));
                }
                q += __shfl_xor_sync(0xffffffffu, q, 1);
                q += __shfl_xor_sync(0xffffffffu, q, 2);
                float rstd = rsqrtf(q * 0.0078125f + 1e-5f);
                float p0 = 0.f, p1 = 0.f;
                #pragma unroll
                for (int nt = 0; nt < 16; nt++) {
                    int col = nt * 8 + 2 * t;
                    float z0 = c[mt][nt][2*rh]   * rstd * sG[col]     + sB2[col];
                    float z1 = c[mt][nt][2*rh+1] * rstd * sG[col + 1] + sB2[col + 1];
                    p0 = fmaf(z0, sW2[col * 2],     fmaf(z1, sW2[(col + 1) * 2],     p0));
                    p1 = fmaf(z0, sW2[col * 2 + 1], fmaf(z1, sW2[(col + 1) * 2 + 1], p1));
                }
                p0 += __shfl_xor_sync(0xffffffffu, p0, 1);
                p0 += __shfl_xor_sync(0xffffffffu, p0, 2);
                p1 += __shfl_xor_sync(0xffffffffu, p1, 1);
                p1 += __shfl_xor_sync(0xffffffffu, p1, 2);
                if (t == 0 && r < N) {
                    out[(size_t)r * 2 + 0] = p0 + b20;
                    out[(size_t)r * 2 + 1] = p1 + b21;
                }
            }
        }
    }
}

// ---------------------------------------------------------------------------
extern "C" void kernel_launch(void* const* d_in, const int* in_sizes, int n_in,
                              void* d_out, int out_size) {
    const float* features = (const float*)d_in[0];
    const int*   ei       = (const int*)  d_in[1];
    const float* ew       = (const float*)d_in[2];
    const float* Wrel     = (const float*)d_in[3];
    const float* Wroot    = (const float*)d_in[4];
    const float* bias     = (const float*)d_in[5];
    const float* lng      = (const float*)d_in[6];
    const float* lnb      = (const float*)d_in[7];
    const float* alpha    = (const float*)d_in[8];
    const float* W1       = (const float*)d_in[9];
    const float* b1       = (const float*)d_in[10];
    const float* cg       = (const float*)d_in[11];
    const float* cb       = (const float*)d_in[12];
    const float* W2       = (const float*)d_in[13];
    const float* b2       = (const float*)d_in[14];

    int N = in_sizes[0] / DD;
    int E = in_sizes[1] / 2;
    int L = in_sizes[8];

    __half *h16a, *h16b, *agg16;
    int *cnt, *off, *bsum;
    uint2 *epack;
    cudaGetSymbolAddress((void**)&h16a,  g_h16a);
    cudaGetSymbolAddress((void**)&h16b,  g_h16b);
    cudaGetSymbolAddress((void**)&agg16, g_agg16);
    cudaGetSymbolAddress((void**)&cnt,   g_cnt);
    cudaGetSymbolAddress((void**)&off,   g_off);
    cudaGetSymbolAddress((void**)&bsum,  g_bsum);
    cudaGetSymbolAddress((void**)&epack, g_epack);

    int sm = 148;
    cudaDeviceGetAttribute(&sm, cudaDevAttrMultiProcessorCount, 0);

    size_t smemL = 65536;   // 2 x 32 KB fp16 B fragments
    size_t smemC = 32768;   // 32 KB
    cudaFuncSetAttribute(layer_mma_kernel, cudaFuncAttributeMaxDynamicSharedMemorySize, (int)smemL);
    cudaFuncSetAttribute(cls_mma_kernel,   cudaFuncAttributeMaxDynamicSharedMemorySize, (int)smemC);

    cudaLaunchAttribute pdlAttr[1];
    pdlAttr[0].id = cudaLaunchAttributeProgrammaticStreamSerialization;
    pdlAttr[0].val.programmaticStreamSerializationAllowed = 1;

    auto mkCfg = [&](int grid, int block, size_t smem) {
        cudaLaunchConfig_t c = {};
        c.gridDim          = dim3(grid, 1, 1);
        c.blockDim         = dim3(block, 1, 1);
        c.dynamicSmemBytes = smem;
        c.attrs            = pdlAttr;
        c.numAttrs         = 1;
        return c;
    };

    // ---- CSR build (PDL chained; no memsets -- cnt self-restores) ----
    int NB = (N + 1023) / 1024;
    {
        cudaLaunchConfig_t c = mkCfg((E + 255) / 256, 256, 0);
        cudaLaunchKernelEx(&c, hist_kernel, ei, cnt, E);
    }
    {
        cudaLaunchConfig_t c = mkCfg(NB, 1024, 0);
        cudaLaunchKernelEx(&c, scan1_kernel, (const int*)cnt, off, bsum, N);
    }
    {
        cudaLaunchConfig_t c = mkCfg(1, 128, 0);
        cudaLaunchKernelEx(&c, scan2_kernel, bsum, off, NB, N);
    }
    {
        cudaLaunchConfig_t c = mkCfg((E + 255) / 256, 256, 0);
        cudaLaunchKernelEx(&c, place_kernel, ei, ew, (const int*)off,
                           (const int*)bsum, cnt, epack, E);
    }

    // fp16 features -> h16a
    int n4 = N * DD / 4;
    {
        cudaLaunchConfig_t c = mkCfg((n4 + 255) / 256, 256, 0);
        cudaLaunchKernelEx(&c, to_half_kernel, (const float4*)features,
                           (uint2*)h16a, n4);
    }

    int gatherBlocks = (N + 7) / 8;

    __half* hin = h16a;
    __half* pong[2] = { h16b, h16a };
    for (int i = 0; i < L; i++) {
        __half* hout = pong[i & 1];
        {
            cudaLaunchConfig_t c = mkCfg(gatherBlocks, 256, 0);
            cudaLaunchKernelEx(&c, gather_kernel,
                               (const __half*)hin, (const int*)off, (const int*)bsum,
                               (const uint2*)epack, agg16, N);
        }
        {
            cudaLaunchConfig_t c = mkCfg(sm, 256, smemL);
            cudaLaunchKernelEx(&c, layer_mma_kernel,
                               (const __half*)hin, (const __half*)agg16,
                               (const float*)(Wrel  + (size_t)i * DD * DD),
                               (const float*)(Wroot + (size_t)i * DD * DD),
                               (const float*)(bias + i * DD), (const float*)(lng + i * DD),
                               (const float*)(lnb + i * DD), (const float*)(alpha + i),
                               hout, N);
        }
        hin = hout;
    }

    {
        cudaLaunchConfig_t c = mkCfg(sm, 256, smemC);
        cudaLaunchKernelEx(&c, cls_mma_kernel,
                           (const __half*)hin, W1, b1, cg, cb, W2, b2,
                           (float*)d_out, N);
    }
}